// round 15
// baseline (speedup 1.0000x reference)
#include <cuda_runtime.h>
#include <cuda_bf16.h>
#include <cstdint>
#include <cstddef>

// ---------------- problem constants ----------------
#define RB 8192
#define RE 256
#define RNE 4096
#define RNL 3
#define K3 768           // split-bf16 K: [hi | lo | hi] x [hi | hi | lo]

// output layout (float32 elements), tuple order:
// x_q [B,E], mean_loss [1], all_idx [B,L], all_oh [B,L,n_e], all_logits [B,L,n_e]
static constexpr size_t LEN_XQ  = (size_t)RB * RE;                 // 2097152
static constexpr size_t OFF_LOSS = LEN_XQ;                         // 2097152
static constexpr size_t OFF_IDX  = OFF_LOSS + 1;                   // 2097153
static constexpr size_t LEN_IDX  = (size_t)RB * RNL;               // 24576
static constexpr size_t OFF_OH   = OFF_IDX + LEN_IDX;              // 2121729
static constexpr size_t LEN_OH   = (size_t)RB * RNL * RNE;         // 100663296
static constexpr size_t OFF_LG   = OFF_OH + LEN_OH;                // 102785025

// ---------------- device scratch ----------------
__device__ float g_res[RB * RE];                  // residual [B,E] fp32
__device__ float g_rr[RB];                        // ||residual_b||^2
__device__ float g_cc[RNL * RNE];                 // ||codebook row||^2 (fp32 exact)
__device__ unsigned long long g_keys[RB];         // packed (dist_bits<<32 | idx)
__device__ float g_lossrow[RB];                   // per-row accumulated sq error
__device__ __nv_bfloat16 g_Ap[(size_t)RB * K3];   // residual split  [hi|lo|hi]
__device__ __nv_bfloat16 g_Bp[(size_t)RNL * RNE * K3]; // codebook split [hi|hi|lo]

// ---------------- PTX helpers (sm_80-era only; no tcgen05 on plain sm_103) ----------------
__device__ __forceinline__ uint32_t smem_u32(const void* p) {
    uint32_t a;
    asm("{ .reg .u64 t; cvta.to.shared.u64 t, %1; cvt.u32.u64 %0, t; }" : "=r"(a) : "l"(p));
    return a;
}
__device__ __forceinline__ void cp16(uint32_t dst, const __nv_bfloat16* src) {
    asm volatile("cp.async.cg.shared.global [%0], [%1], 16;\n" :: "r"(dst),
                 "l"(__cvta_generic_to_global(src)));
}
__device__ __forceinline__ void cp_commit() {
    asm volatile("cp.async.commit_group;\n" ::: "memory");
}
template <int N>
__device__ __forceinline__ void cp_wait() {
    asm volatile("cp.async.wait_group %0;\n" :: "n"(N) : "memory");
}
__device__ __forceinline__ void ldsm4(uint32_t* r, uint32_t addr) {
    asm volatile("ldmatrix.sync.aligned.m8n8.x4.shared.b16 {%0,%1,%2,%3}, [%4];"
                 : "=r"(r[0]), "=r"(r[1]), "=r"(r[2]), "=r"(r[3]) : "r"(addr));
}
__device__ __forceinline__ void mma16816(float* c, const uint32_t* a, const uint32_t* b) {
    asm volatile(
        "mma.sync.aligned.m16n8k16.row.col.f32.bf16.bf16.f32 "
        "{%0,%1,%2,%3}, {%4,%5,%6,%7}, {%8,%9}, {%0,%1,%2,%3};"
        : "+f"(c[0]), "+f"(c[1]), "+f"(c[2]), "+f"(c[3])
        : "r"(a[0]), "r"(a[1]), "r"(a[2]), "r"(a[3]), "r"(b[0]), "r"(b[1]));
}

// split fp32 -> (hi, lo) bf16
__device__ __forceinline__ void split1(float x, __nv_bfloat16& h, __nv_bfloat16& l) {
    h = __float2bfloat16(x);
    l = __float2bfloat16(__fsub_rn(x, __bfloat162float(h)));
}

// ---------------- init helpers ----------------
__device__ __forceinline__ void init_row(const float* __restrict__ x, float* __restrict__ out,
                                         int b, int t) {
    float4 v = *(const float4*)(x + (size_t)b * RE + t * 4);
    *(float4*)(g_res + (size_t)b * RE + t * 4) = v;
    *(float4*)(out + (size_t)b * RE + t * 4) = make_float4(0.f, 0.f, 0.f, 0.f);

    __nv_bfloat16 h0, h1, h2, h3, l0, l1, l2, l3;
    split1(v.x, h0, l0); split1(v.y, h1, l1); split1(v.z, h2, l2); split1(v.w, h3, l3);
    __nv_bfloat16* ap = g_Ap + (size_t)b * K3 + t * 4;
    *(__nv_bfloat162*)(ap + 0) = __nv_bfloat162(h0, h1);
    *(__nv_bfloat162*)(ap + 2) = __nv_bfloat162(h2, h3);
    *(__nv_bfloat162*)(ap + 256) = __nv_bfloat162(l0, l1);
    *(__nv_bfloat162*)(ap + 258) = __nv_bfloat162(l2, l3);
    *(__nv_bfloat162*)(ap + 512) = __nv_bfloat162(h0, h1);
    *(__nv_bfloat162*)(ap + 514) = __nv_bfloat162(h2, h3);

    float s = v.x * v.x + v.y * v.y + v.z * v.z + v.w * v.w;
    for (int o = 16; o > 0; o >>= 1) s += __shfl_down_sync(0xffffffffu, s, o);
    __shared__ float sm[2];
    if ((t & 31) == 0) sm[t >> 5] = s;
    __syncthreads();
    if (t == 0) {
        g_rr[b] = sm[0] + sm[1];
        g_keys[b] = 0xFFFFFFFFFFFFFFFFULL;
        g_lossrow[b] = 0.f;
    }
}

__device__ __forceinline__ void init_cb(const float* __restrict__ cbs, int i, int t) {
    float4 v = *(const float4*)(cbs + (size_t)i * RE + t * 4);
    __nv_bfloat16 h0, h1, h2, h3, l0, l1, l2, l3;
    split1(v.x, h0, l0); split1(v.y, h1, l1); split1(v.z, h2, l2); split1(v.w, h3, l3);
    __nv_bfloat16* bp = g_Bp + (size_t)i * K3 + t * 4;
    *(__nv_bfloat162*)(bp + 0) = __nv_bfloat162(h0, h1);
    *(__nv_bfloat162*)(bp + 2) = __nv_bfloat162(h2, h3);
    *(__nv_bfloat162*)(bp + 256) = __nv_bfloat162(h0, h1);
    *(__nv_bfloat162*)(bp + 258) = __nv_bfloat162(h2, h3);
    *(__nv_bfloat162*)(bp + 512) = __nv_bfloat162(l0, l1);
    *(__nv_bfloat162*)(bp + 514) = __nv_bfloat162(l2, l3);

    float s = v.x * v.x + v.y * v.y + v.z * v.z + v.w * v.w;
    for (int o = 16; o > 0; o >>= 1) s += __shfl_down_sync(0xffffffffu, s, o);
    __shared__ float sm[2];
    if ((t & 31) == 0) sm[t >> 5] = s;
    __syncthreads();
    if (t == 0) g_cc[i] = sm[0] + sm[1];
}

// half A: rows [0, RB/2) + codebook layer 0
__global__ void k_init_a(const float* __restrict__ x, const float* __restrict__ cbs,
                         float* __restrict__ out) {
    int blk = blockIdx.x, t = threadIdx.x;  // RB/2 + RNE blocks, 64 threads
    if (blk < RB / 2) init_row(x, out, blk, t);
    else init_cb(cbs, blk - RB / 2, t);
}
// half B: rows [RB/2, RB) + codebook layers 1..2
__global__ void k_init_b(const float* __restrict__ x, const float* __restrict__ cbs,
                         float* __restrict__ out) {
    int blk = blockIdx.x, t = threadIdx.x;  // RB/2 + 2*RNE blocks
    if (blk < RB / 2) init_row(x, out, RB / 2 + blk, t);
    else init_cb(cbs, RNE + (blk - RB / 2), t);
}

// ---------------- mma.sync distance GEMM + logits + OH-zero + argmin ----------------
// CTA 128x128, 4 warps (2m x 2n), warp tile 64x64, K=768 in 12 chunks of 64.
// 3-stage cp.async pipeline (32KB/stage), ONE __syncthreads per chunk.
// Also zeroes its one-hot tile (k_update writes the 1.0s afterwards, same stream).
// Grid = (32, 32) per row-half; m_base selects the half.
#define DYN_SM 99328

__global__ void __launch_bounds__(128, 2) k_dist_tc(int l, int m_base, float* __restrict__ out) {
    extern __shared__ __align__(16) char smraw[];
    uint32_t rawb = smem_u32(smraw);
    uint32_t sbase = (rawb + 1023u) & ~1023u;
    float* ep = (float*)(smraw + (sbase - rawb));  // epilogue staging [128][132]

    int tid = threadIdx.x, wid = tid >> 5, lane = tid & 31;
    int n0 = blockIdx.x * 128, m0 = m_base + blockIdx.y * 128;
    int warp_m = wid >> 1, warp_n = wid & 1;
    int mbw = warp_m * 64, nbw = warp_n * 64;
    int g = lane >> 2, tig = lane & 3;

    const __nv_bfloat16* Ap = g_Ap;
    const __nv_bfloat16* Bp = g_Bp + (size_t)l * RNE * K3;
    const float* ccn = g_cc + l * RNE;

    // per-lane ldmatrix address pieces (4 A frags of m16, 4 B frags of n16)
    uint32_t arow[4], axor[4], brow[4], bxor[4];
#pragma unroll
    for (int i = 0; i < 4; i++) {
        int r = mbw + i * 16 + ((lane >> 3) & 1) * 8 + (lane & 7);
        arow[i] = (uint32_t)r * 128u;
        axor[i] = (uint32_t)((r & 7) << 4);
    }
    uint32_t koffA = (uint32_t)(((lane >> 4) & 1) * 16);
#pragma unroll
    for (int j2 = 0; j2 < 4; j2++) {
        int r = nbw + j2 * 16 + ((lane >> 4) & 1) * 8 + (lane & 7);
        brow[j2] = (uint32_t)r * 128u;
        bxor[j2] = (uint32_t)((r & 7) << 4);
    }
    uint32_t koffB = (uint32_t)(((lane >> 3) & 1) * 16);

    float acc[4][8][4];
#pragma unroll
    for (int i = 0; i < 4; i++)
#pragma unroll
        for (int j = 0; j < 8; j++)
#pragma unroll
            for (int r = 0; r < 4; r++) acc[i][j][r] = 0.f;

    // chunk loader: 128 rows x 64 bf16 (128B rows), SW128 swizzle, A then B
    auto load_chunk = [&](int c, int s) {
        uint32_t ab = sbase + s * 32768;
        uint32_t bb = ab + 16384;
        const __nv_bfloat16* ag = Ap + (size_t)m0 * K3 + c * 64;
        const __nv_bfloat16* bg = Bp + (size_t)n0 * K3 + c * 64;
#pragma unroll
        for (int i = 0; i < 8; i++) {
            int idx = tid + i * 128;
            int row = idx >> 3, q = idx & 7;
            uint32_t off = row * 128 + q * 16;
            uint32_t sw = off ^ ((off >> 3) & 0x70);
            cp16(ab + sw, ag + (size_t)row * K3 + q * 8);
        }
#pragma unroll
        for (int i = 0; i < 8; i++) {
            int idx = tid + i * 128;
            int row = idx >> 3, q = idx & 7;
            uint32_t off = row * 128 + q * 16;
            uint32_t sw = off ^ ((off >> 3) & 0x70);
            cp16(bb + sw, bg + (size_t)row * K3 + q * 8);
        }
        cp_commit();
    };

    load_chunk(0, 0);
    load_chunk(1, 1);
    int stage_next = 2;
    for (int c = 0; c < 12; c++) {
        int s = c % 3;
        if (c == 11) cp_wait<0>(); else cp_wait<1>();
        __syncthreads();  // chunk c visible; orders prior readers vs upcoming overwrite

        uint32_t sA = sbase + s * 32768;
        uint32_t sB = sA + 16384;
#pragma unroll
        for (int ks = 0; ks < 4; ks++) {
            uint32_t a[4][4], b[4][4];
#pragma unroll
            for (int i = 0; i < 4; i++)
                ldsm4(a[i], sA + arow[i] + (((uint32_t)(ks * 32) + koffA) ^ axor[i]));
#pragma unroll
            for (int j2 = 0; j2 < 4; j2++)
                ldsm4(b[j2], sB + brow[j2] + (((uint32_t)(ks * 32) + koffB) ^ bxor[j2]));
#pragma unroll
            for (int i = 0; i < 4; i++)
#pragma unroll
                for (int j = 0; j < 8; j++)
                    mma16816(acc[i][j], a[i], &b[j >> 1][(j & 1) * 2]);
        }
        if (c + 2 < 12) {
            load_chunk(c + 2, stage_next);
            stage_next = (stage_next + 1) % 3;
        }
    }
    __syncthreads();  // all warps done reading stages before epilogue reuses smem

    // ---- epilogue: d = (rr + cc) - 2*dot, argmin keys, stage logits ----
    float cc0[8], cc1[8];
#pragma unroll
    for (int j = 0; j < 8; j++) {
        cc0[j] = ccn[n0 + nbw + j * 8 + tig * 2];
        cc1[j] = ccn[n0 + nbw + j * 8 + tig * 2 + 1];
    }
#pragma unroll
    for (int i = 0; i < 4; i++) {
        int r0 = mbw + i * 16 + g, r1 = r0 + 8;
        float rr0 = g_rr[m0 + r0], rr1 = g_rr[m0 + r1];
        unsigned long long b0 = 0xFFFFFFFFFFFFFFFFULL, b1 = b0;
#pragma unroll
        for (int j = 0; j < 8; j++) {
            int coln = nbw + j * 8 + tig * 2;
            unsigned nlo = (unsigned)(n0 + coln), nhi = nlo + 1;
            float d00 = __fadd_rn(__fadd_rn(rr0, cc0[j]), -2.0f * acc[i][j][0]);
            float d01 = __fadd_rn(__fadd_rn(rr0, cc1[j]), -2.0f * acc[i][j][1]);
            float d10 = __fadd_rn(__fadd_rn(rr1, cc0[j]), -2.0f * acc[i][j][2]);
            float d11 = __fadd_rn(__fadd_rn(rr1, cc1[j]), -2.0f * acc[i][j][3]);
            *(float2*)(ep + r0 * 132 + coln) = make_float2(d00, d01);
            *(float2*)(ep + r1 * 132 + coln) = make_float2(d10, d11);
            unsigned long long k00 = ((unsigned long long)__float_as_uint(d00) << 32) | nlo;
            unsigned long long k01 = ((unsigned long long)__float_as_uint(d01) << 32) | nhi;
            unsigned long long k10 = ((unsigned long long)__float_as_uint(d10) << 32) | nlo;
            unsigned long long k11 = ((unsigned long long)__float_as_uint(d11) << 32) | nhi;
            if (k00 < b0) b0 = k00;
            if (k01 < b0) b0 = k01;
            if (k10 < b1) b1 = k10;
            if (k11 < b1) b1 = k11;
        }
        b0 = min(b0, __shfl_xor_sync(0xffffffffu, b0, 1));
        b0 = min(b0, __shfl_xor_sync(0xffffffffu, b0, 2));
        b1 = min(b1, __shfl_xor_sync(0xffffffffu, b1, 1));
        b1 = min(b1, __shfl_xor_sync(0xffffffffu, b1, 2));
        if (tig == 0) {
            atomicMin(&g_keys[m0 + r0], b0);
            atomicMin(&g_keys[m0 + r1], b1);
        }
    }
    __syncthreads();

    // coalesced stores: logits tile + zero of the matching one-hot tile
    for (int r = 0; r < 128; r++) {
        size_t rowbase = ((size_t)(m0 + r) * RNL + l) * RNE + n0 + tid;
        out[OFF_LG + rowbase] = ep[r * 132 + tid];
        out[OFF_OH + rowbase] = 0.0f;
    }
}

// ---------------- per-row gather/update: 256 threads, 4 rows per block ----------------
// Writes the one-hot 1.0 directly (its OH tile was zeroed by dist in the same stream).
__global__ void k_update(const float* __restrict__ cbs, int l, int row_base,
                         float* __restrict__ out) {
    int tid = threadIdx.x;
    int grp = tid >> 6;          // 0..3 (four 64-thread groups = 4 rows)
    int sub = tid & 63;          // position within row
    int lane = tid & 31;
    int whalf = (tid >> 5) & 1;  // warp half within group
    int b = row_base + blockIdx.x * 4 + grp;

    unsigned long long key = g_keys[b];
    unsigned idx = (unsigned)(key & 0xFFFFFFFFULL);
    const float* cbL = cbs + (size_t)l * RNE * RE;
    float4 c4 = *(const float4*)(cbL + (size_t)idx * RE + sub * 4);
    float4 r4 = *(float4*)(g_res + (size_t)b * RE + sub * 4);

    float sq = 0.f, rrn = 0.f;
    float4 xres, nr;
#define STEP(comp)                                           \
    {                                                        \
        float df = __fsub_rn(c4.comp, r4.comp);              \
        float xr = __fadd_rn(r4.comp, df);                   \
        float nv = __fsub_rn(r4.comp, xr);                   \
        sq = fmaf(df, df, sq); rrn = fmaf(nv, nv, rrn);      \
        xres.comp = xr; nr.comp = nv;                        \
    }
    STEP(x) STEP(y) STEP(z) STEP(w)
#undef STEP

    *(float4*)(g_res + (size_t)b * RE + sub * 4) = nr;

    if (l < RNL - 1) {  // refresh A' for next layer
        __nv_bfloat16 h0, h1, h2, h3, l0, l1, l2, l3;
        split1(nr.x, h0, l0); split1(nr.y, h1, l1); split1(nr.z, h2, l2); split1(nr.w, h3, l3);
        __nv_bfloat16* ap = g_Ap + (size_t)b * K3 + sub * 4;
        *(__nv_bfloat162*)(ap + 0) = __nv_bfloat162(h0, h1);
        *(__nv_bfloat162*)(ap + 2) = __nv_bfloat162(h2, h3);
        *(__nv_bfloat162*)(ap + 256) = __nv_bfloat162(l0, l1);
        *(__nv_bfloat162*)(ap + 258) = __nv_bfloat162(l2, l3);
        *(__nv_bfloat162*)(ap + 512) = __nv_bfloat162(h0, h1);
        *(__nv_bfloat162*)(ap + 514) = __nv_bfloat162(h2, h3);
    }

    float4* xq = (float4*)(out + (size_t)b * RE) + sub;
    float4 q = *xq;
    q.x += xres.x; q.y += xres.y; q.z += xres.z; q.w += xres.w;
    *xq = q;

    for (int o = 16; o > 0; o >>= 1) {
        sq += __shfl_down_sync(0xffffffffu, sq, o);
        rrn += __shfl_down_sync(0xffffffffu, rrn, o);
    }
    __shared__ float s_red[4][2][2];
    if (lane == 0) { s_red[grp][whalf][0] = sq; s_red[grp][whalf][1] = rrn; }
    __syncthreads();
    if (sub == 0) {
        g_lossrow[b] += s_red[grp][0][0] + s_red[grp][1][0];
        g_rr[b] = s_red[grp][0][1] + s_red[grp][1][1];
        out[OFF_IDX + (size_t)b * RNL + l] = (float)idx;
        out[OFF_OH + ((size_t)b * RNL + l) * RNE + idx] = 1.0f;
        g_keys[b] = 0xFFFFFFFFFFFFFFFFULL;   // reset for next layer
    }
}

// ---------------- deterministic final loss ----------------
__global__ void k_finish(float* __restrict__ out) {
    __shared__ float sm[256];
    int t = threadIdx.x;
    float s = 0.f;
    for (int i = t; i < RB; i += 256) s += g_lossrow[i];
    sm[t] = s;
    __syncthreads();
    for (int o = 128; o > 0; o >>= 1) {
        if (t < o) sm[t] += sm[t + o];
        __syncthreads();
    }
    if (t == 0) out[OFF_LOSS] = sm[0] * (1.25f / (3.0f * RB * RE));
}

// ---------------- launch: 2 streams, 4 events, 15 kernels ----------------
extern "C" void kernel_launch(void* const* d_in, const int* in_sizes, int n_in,
                              void* d_out, int out_size) {
    const float* x = (const float*)d_in[0];
    const float* cbs = (const float*)d_in[1];
    float* out = (float*)d_out;

    cudaFuncSetAttribute(k_dist_tc, cudaFuncAttributeMaxDynamicSharedMemorySize, DYN_SM);

    cudaStream_t sH1;
    cudaStreamCreateWithFlags(&sH1, cudaStreamNonBlocking);
    cudaEvent_t eRoot, eA, eB, eH1;
    cudaEventCreateWithFlags(&eRoot, cudaEventDisableTiming);
    cudaEventCreateWithFlags(&eA, cudaEventDisableTiming);
    cudaEventCreateWithFlags(&eB, cudaEventDisableTiming);
    cudaEventCreateWithFlags(&eH1, cudaEventDisableTiming);

    cudaEventRecord(eRoot, 0);
    cudaStreamWaitEvent(sH1, eRoot, 0);

    // split init: main = rows h0 + cb layer 0; sH1 = rows h1 + cb layers 1,2
    k_init_a<<<RB / 2 + RNE, 64, 0, 0>>>(x, cbs, out);
    cudaEventRecord(eA, 0);
    k_init_b<<<RB / 2 + 2 * RNE, 64, 0, sH1>>>(x, cbs, out);
    cudaEventRecord(eB, sH1);
    cudaStreamWaitEvent(sH1, eA, 0);  // h1's layer-0 dist needs cb0 (from main)

    for (int l = 0; l < RNL; l++) {
        if (l == 1) cudaStreamWaitEvent(0, eB, 0);  // main's layer-1 dist needs cb1/2
        k_dist_tc<<<dim3(32, 32), 128, DYN_SM, 0>>>(l, 0, out);
        k_update<<<RB / 8, 256, 0, 0>>>(cbs, l, 0, out);
        k_dist_tc<<<dim3(32, 32), 128, DYN_SM, sH1>>>(l, RB / 2, out);
        k_update<<<RB / 8, 256, 0, sH1>>>(cbs, l, RB / 2, out);
    }

    cudaEventRecord(eH1, sH1);
    cudaStreamWaitEvent(0, eH1, 0);
    k_finish<<<1, 256>>>(out);
}

// round 16
// speedup vs baseline: 1.0138x; 1.0138x over previous
#include <cuda_runtime.h>
#include <cuda_bf16.h>
#include <cstdint>
#include <cstddef>

// ---------------- problem constants ----------------
#define RB 8192
#define RE 256
#define RNE 4096
#define RNL 3
#define K3 768           // split-bf16 K: [hi | lo | hi] x [hi | hi | lo]

// output layout (float32 elements), tuple order:
// x_q [B,E], mean_loss [1], all_idx [B,L], all_oh [B,L,n_e], all_logits [B,L,n_e]
static constexpr size_t LEN_XQ  = (size_t)RB * RE;                 // 2097152
static constexpr size_t OFF_LOSS = LEN_XQ;                         // 2097152
static constexpr size_t OFF_IDX  = OFF_LOSS + 1;                   // 2097153
static constexpr size_t LEN_IDX  = (size_t)RB * RNL;               // 24576
static constexpr size_t OFF_OH   = OFF_IDX + LEN_IDX;              // 2121729
static constexpr size_t LEN_OH   = (size_t)RB * RNL * RNE;         // 100663296
static constexpr size_t OFF_LG   = OFF_OH + LEN_OH;                // 102785025

// ---------------- device scratch ----------------
__device__ float g_res[RB * RE];                  // residual [B,E] fp32
__device__ float g_rr[RB];                        // ||residual_b||^2
__device__ float g_cc[RNL * RNE];                 // ||codebook row||^2 (fp32 exact)
__device__ unsigned long long g_keys[RB];         // packed (dist_bits<<32 | idx)
__device__ float g_lossrow[RB];                   // per-row accumulated sq error
__device__ __nv_bfloat16 g_Ap[(size_t)RB * K3];   // residual split  [hi|lo|hi]
__device__ __nv_bfloat16 g_Bp[(size_t)RNL * RNE * K3]; // codebook split [hi|hi|lo]

// ---------------- PTX helpers (sm_80-era only; no tcgen05 on plain sm_103) ----------------
__device__ __forceinline__ uint32_t smem_u32(const void* p) {
    uint32_t a;
    asm("{ .reg .u64 t; cvta.to.shared.u64 t, %1; cvt.u32.u64 %0, t; }" : "=r"(a) : "l"(p));
    return a;
}
__device__ __forceinline__ void cp16(uint32_t dst, const __nv_bfloat16* src) {
    asm volatile("cp.async.cg.shared.global [%0], [%1], 16;\n" :: "r"(dst),
                 "l"(__cvta_generic_to_global(src)));
}
__device__ __forceinline__ void cp_commit() {
    asm volatile("cp.async.commit_group;\n" ::: "memory");
}
template <int N>
__device__ __forceinline__ void cp_wait() {
    asm volatile("cp.async.wait_group %0;\n" :: "n"(N) : "memory");
}
__device__ __forceinline__ void ldsm4(uint32_t* r, uint32_t addr) {
    asm volatile("ldmatrix.sync.aligned.m8n8.x4.shared.b16 {%0,%1,%2,%3}, [%4];"
                 : "=r"(r[0]), "=r"(r[1]), "=r"(r[2]), "=r"(r[3]) : "r"(addr));
}
__device__ __forceinline__ void mma16816(float* c, const uint32_t* a, const uint32_t* b) {
    asm volatile(
        "mma.sync.aligned.m16n8k16.row.col.f32.bf16.bf16.f32 "
        "{%0,%1,%2,%3}, {%4,%5,%6,%7}, {%8,%9}, {%0,%1,%2,%3};"
        : "+f"(c[0]), "+f"(c[1]), "+f"(c[2]), "+f"(c[3])
        : "r"(a[0]), "r"(a[1]), "r"(a[2]), "r"(a[3]), "r"(b[0]), "r"(b[1]));
}

// split fp32 -> (hi, lo) bf16
__device__ __forceinline__ void split1(float x, __nv_bfloat16& h, __nv_bfloat16& l) {
    h = __float2bfloat16(x);
    l = __float2bfloat16(__fsub_rn(x, __bfloat162float(h)));
}

// ---------------- merged init: rows (residual/xq/rr/keys/loss/A') + codebook (B'/cc) ----------------
__global__ void k_init_all(const float* __restrict__ x, const float* __restrict__ cbs,
                           float* __restrict__ out) {
    int blk = blockIdx.x, t = threadIdx.x;  // 64 threads
    if (blk < RB) {
        int b = blk;
        float4 v = *(const float4*)(x + (size_t)b * RE + t * 4);
        *(float4*)(g_res + (size_t)b * RE + t * 4) = v;
        *(float4*)(out + (size_t)b * RE + t * 4) = make_float4(0.f, 0.f, 0.f, 0.f);

        __nv_bfloat16 h0, h1, h2, h3, l0, l1, l2, l3;
        split1(v.x, h0, l0); split1(v.y, h1, l1); split1(v.z, h2, l2); split1(v.w, h3, l3);
        __nv_bfloat16* ap = g_Ap + (size_t)b * K3 + t * 4;
        *(__nv_bfloat162*)(ap + 0) = __nv_bfloat162(h0, h1);
        *(__nv_bfloat162*)(ap + 2) = __nv_bfloat162(h2, h3);
        *(__nv_bfloat162*)(ap + 256) = __nv_bfloat162(l0, l1);
        *(__nv_bfloat162*)(ap + 258) = __nv_bfloat162(l2, l3);
        *(__nv_bfloat162*)(ap + 512) = __nv_bfloat162(h0, h1);
        *(__nv_bfloat162*)(ap + 514) = __nv_bfloat162(h2, h3);

        float s = v.x * v.x + v.y * v.y + v.z * v.z + v.w * v.w;
        for (int o = 16; o > 0; o >>= 1) s += __shfl_down_sync(0xffffffffu, s, o);
        __shared__ float sm[2];
        if ((t & 31) == 0) sm[t >> 5] = s;
        __syncthreads();
        if (t == 0) {
            g_rr[b] = sm[0] + sm[1];
            g_keys[b] = 0xFFFFFFFFFFFFFFFFULL;
            g_lossrow[b] = 0.f;
        }
    } else {
        int i = blk - RB;  // [0, RNL*RNE)
        float4 v = *(const float4*)(cbs + (size_t)i * RE + t * 4);
        __nv_bfloat16 h0, h1, h2, h3, l0, l1, l2, l3;
        split1(v.x, h0, l0); split1(v.y, h1, l1); split1(v.z, h2, l2); split1(v.w, h3, l3);
        __nv_bfloat16* bp = g_Bp + (size_t)i * K3 + t * 4;
        *(__nv_bfloat162*)(bp + 0) = __nv_bfloat162(h0, h1);
        *(__nv_bfloat162*)(bp + 2) = __nv_bfloat162(h2, h3);
        *(__nv_bfloat162*)(bp + 256) = __nv_bfloat162(h0, h1);
        *(__nv_bfloat162*)(bp + 258) = __nv_bfloat162(h2, h3);
        *(__nv_bfloat162*)(bp + 512) = __nv_bfloat162(l0, l1);
        *(__nv_bfloat162*)(bp + 514) = __nv_bfloat162(l2, l3);

        float s = v.x * v.x + v.y * v.y + v.z * v.z + v.w * v.w;
        for (int o = 16; o > 0; o >>= 1) s += __shfl_down_sync(0xffffffffu, s, o);
        __shared__ float sm[2];
        if ((t & 31) == 0) sm[t >> 5] = s;
        __syncthreads();
        if (t == 0) g_cc[i] = sm[0] + sm[1];
    }
}

// ---------------- mma.sync distance GEMM + logits + OH-zero + argmin ----------------
// CTA 128x128, 4 warps (2m x 2n), warp tile 64x64, K=768 in 12 chunks of 64.
// 3-stage cp.async pipeline (32KB/stage), ONE __syncthreads per chunk.
// Also zeroes its one-hot tile (k_update writes the 1.0s afterwards, same stream).
// Grid = (32, 32) per row-half; m_base selects the half.
#define DYN_SM 99328

__global__ void __launch_bounds__(128, 2) k_dist_tc(int l, int m_base, float* __restrict__ out) {
    extern __shared__ __align__(16) char smraw[];
    uint32_t rawb = smem_u32(smraw);
    uint32_t sbase = (rawb + 1023u) & ~1023u;
    float* ep = (float*)(smraw + (sbase - rawb));  // epilogue staging [128][132]

    int tid = threadIdx.x, wid = tid >> 5, lane = tid & 31;
    int n0 = blockIdx.x * 128, m0 = m_base + blockIdx.y * 128;
    int warp_m = wid >> 1, warp_n = wid & 1;
    int mbw = warp_m * 64, nbw = warp_n * 64;
    int g = lane >> 2, tig = lane & 3;

    const __nv_bfloat16* Ap = g_Ap;
    const __nv_bfloat16* Bp = g_Bp + (size_t)l * RNE * K3;
    const float* ccn = g_cc + l * RNE;

    // per-lane ldmatrix address pieces (4 A frags of m16, 4 B frags of n16)
    uint32_t arow[4], axor[4], brow[4], bxor[4];
#pragma unroll
    for (int i = 0; i < 4; i++) {
        int r = mbw + i * 16 + ((lane >> 3) & 1) * 8 + (lane & 7);
        arow[i] = (uint32_t)r * 128u;
        axor[i] = (uint32_t)((r & 7) << 4);
    }
    uint32_t koffA = (uint32_t)(((lane >> 4) & 1) * 16);
#pragma unroll
    for (int j2 = 0; j2 < 4; j2++) {
        int r = nbw + j2 * 16 + ((lane >> 4) & 1) * 8 + (lane & 7);
        brow[j2] = (uint32_t)r * 128u;
        bxor[j2] = (uint32_t)((r & 7) << 4);
    }
    uint32_t koffB = (uint32_t)(((lane >> 3) & 1) * 16);

    float acc[4][8][4];
#pragma unroll
    for (int i = 0; i < 4; i++)
#pragma unroll
        for (int j = 0; j < 8; j++)
#pragma unroll
            for (int r = 0; r < 4; r++) acc[i][j][r] = 0.f;

    // chunk loader: 128 rows x 64 bf16 (128B rows), SW128 swizzle, A then B
    auto load_chunk = [&](int c, int s) {
        uint32_t ab = sbase + s * 32768;
        uint32_t bb = ab + 16384;
        const __nv_bfloat16* ag = Ap + (size_t)m0 * K3 + c * 64;
        const __nv_bfloat16* bg = Bp + (size_t)n0 * K3 + c * 64;
#pragma unroll
        for (int i = 0; i < 8; i++) {
            int idx = tid + i * 128;
            int row = idx >> 3, q = idx & 7;
            uint32_t off = row * 128 + q * 16;
            uint32_t sw = off ^ ((off >> 3) & 0x70);
            cp16(ab + sw, ag + (size_t)row * K3 + q * 8);
        }
#pragma unroll
        for (int i = 0; i < 8; i++) {
            int idx = tid + i * 128;
            int row = idx >> 3, q = idx & 7;
            uint32_t off = row * 128 + q * 16;
            uint32_t sw = off ^ ((off >> 3) & 0x70);
            cp16(bb + sw, bg + (size_t)row * K3 + q * 8);
        }
        cp_commit();
    };

    load_chunk(0, 0);
    load_chunk(1, 1);
    int stage_next = 2;
    for (int c = 0; c < 12; c++) {
        int s = c % 3;
        if (c == 11) cp_wait<0>(); else cp_wait<1>();
        __syncthreads();  // chunk c visible; orders prior readers vs upcoming overwrite

        uint32_t sA = sbase + s * 32768;
        uint32_t sB = sA + 16384;
#pragma unroll
        for (int ks = 0; ks < 4; ks++) {
            uint32_t a[4][4], b[4][4];
#pragma unroll
            for (int i = 0; i < 4; i++)
                ldsm4(a[i], sA + arow[i] + (((uint32_t)(ks * 32) + koffA) ^ axor[i]));
#pragma unroll
            for (int j2 = 0; j2 < 4; j2++)
                ldsm4(b[j2], sB + brow[j2] + (((uint32_t)(ks * 32) + koffB) ^ bxor[j2]));
#pragma unroll
            for (int i = 0; i < 4; i++)
#pragma unroll
                for (int j = 0; j < 8; j++)
                    mma16816(acc[i][j], a[i], &b[j >> 1][(j & 1) * 2]);
        }
        if (c + 2 < 12) {
            load_chunk(c + 2, stage_next);
            stage_next = (stage_next + 1) % 3;
        }
    }
    __syncthreads();  // all warps done reading stages before epilogue reuses smem

    // ---- epilogue: d = (rr + cc) - 2*dot, argmin keys, stage logits ----
    float cc0[8], cc1[8];
#pragma unroll
    for (int j = 0; j < 8; j++) {
        cc0[j] = ccn[n0 + nbw + j * 8 + tig * 2];
        cc1[j] = ccn[n0 + nbw + j * 8 + tig * 2 + 1];
    }
#pragma unroll
    for (int i = 0; i < 4; i++) {
        int r0 = mbw + i * 16 + g, r1 = r0 + 8;
        float rr0 = g_rr[m0 + r0], rr1 = g_rr[m0 + r1];
        unsigned long long b0 = 0xFFFFFFFFFFFFFFFFULL, b1 = b0;
#pragma unroll
        for (int j = 0; j < 8; j++) {
            int coln = nbw + j * 8 + tig * 2;
            unsigned nlo = (unsigned)(n0 + coln), nhi = nlo + 1;
            float d00 = __fadd_rn(__fadd_rn(rr0, cc0[j]), -2.0f * acc[i][j][0]);
            float d01 = __fadd_rn(__fadd_rn(rr0, cc1[j]), -2.0f * acc[i][j][1]);
            float d10 = __fadd_rn(__fadd_rn(rr1, cc0[j]), -2.0f * acc[i][j][2]);
            float d11 = __fadd_rn(__fadd_rn(rr1, cc1[j]), -2.0f * acc[i][j][3]);
            *(float2*)(ep + r0 * 132 + coln) = make_float2(d00, d01);
            *(float2*)(ep + r1 * 132 + coln) = make_float2(d10, d11);
            unsigned long long k00 = ((unsigned long long)__float_as_uint(d00) << 32) | nlo;
            unsigned long long k01 = ((unsigned long long)__float_as_uint(d01) << 32) | nhi;
            unsigned long long k10 = ((unsigned long long)__float_as_uint(d10) << 32) | nlo;
            unsigned long long k11 = ((unsigned long long)__float_as_uint(d11) << 32) | nhi;
            if (k00 < b0) b0 = k00;
            if (k01 < b0) b0 = k01;
            if (k10 < b1) b1 = k10;
            if (k11 < b1) b1 = k11;
        }
        b0 = min(b0, __shfl_xor_sync(0xffffffffu, b0, 1));
        b0 = min(b0, __shfl_xor_sync(0xffffffffu, b0, 2));
        b1 = min(b1, __shfl_xor_sync(0xffffffffu, b1, 1));
        b1 = min(b1, __shfl_xor_sync(0xffffffffu, b1, 2));
        if (tig == 0) {
            atomicMin(&g_keys[m0 + r0], b0);
            atomicMin(&g_keys[m0 + r1], b1);
        }
    }
    __syncthreads();

    // coalesced stores: logits tile + zero of the matching one-hot tile
    for (int r = 0; r < 128; r++) {
        size_t rowbase = ((size_t)(m0 + r) * RNL + l) * RNE + n0 + tid;
        out[OFF_LG + rowbase] = ep[r * 132 + tid];
        out[OFF_OH + rowbase] = 0.0f;
    }
}

// ---------------- per-row gather/update: 256 threads, 4 rows per block ----------------
// Writes the one-hot 1.0 directly (its OH tile was zeroed by dist in the same stream).
__global__ void k_update(const float* __restrict__ cbs, int l, int row_base,
                         float* __restrict__ out) {
    int tid = threadIdx.x;
    int grp = tid >> 6;          // 0..3 (four 64-thread groups = 4 rows)
    int sub = tid & 63;          // position within row
    int lane = tid & 31;
    int whalf = (tid >> 5) & 1;  // warp half within group
    int b = row_base + blockIdx.x * 4 + grp;

    unsigned long long key = g_keys[b];
    unsigned idx = (unsigned)(key & 0xFFFFFFFFULL);
    const float* cbL = cbs + (size_t)l * RNE * RE;
    float4 c4 = *(const float4*)(cbL + (size_t)idx * RE + sub * 4);
    float4 r4 = *(float4*)(g_res + (size_t)b * RE + sub * 4);

    float sq = 0.f, rrn = 0.f;
    float4 xres, nr;
#define STEP(comp)                                           \
    {                                                        \
        float df = __fsub_rn(c4.comp, r4.comp);              \
        float xr = __fadd_rn(r4.comp, df);                   \
        float nv = __fsub_rn(r4.comp, xr);                   \
        sq = fmaf(df, df, sq); rrn = fmaf(nv, nv, rrn);      \
        xres.comp = xr; nr.comp = nv;                        \
    }
    STEP(x) STEP(y) STEP(z) STEP(w)
#undef STEP

    *(float4*)(g_res + (size_t)b * RE + sub * 4) = nr;

    if (l < RNL - 1) {  // refresh A' for next layer
        __nv_bfloat16 h0, h1, h2, h3, l0, l1, l2, l3;
        split1(nr.x, h0, l0); split1(nr.y, h1, l1); split1(nr.z, h2, l2); split1(nr.w, h3, l3);
        __nv_bfloat16* ap = g_Ap + (size_t)b * K3 + sub * 4;
        *(__nv_bfloat162*)(ap + 0) = __nv_bfloat162(h0, h1);
        *(__nv_bfloat162*)(ap + 2) = __nv_bfloat162(h2, h3);
        *(__nv_bfloat162*)(ap + 256) = __nv_bfloat162(l0, l1);
        *(__nv_bfloat162*)(ap + 258) = __nv_bfloat162(l2, l3);
        *(__nv_bfloat162*)(ap + 512) = __nv_bfloat162(h0, h1);
        *(__nv_bfloat162*)(ap + 514) = __nv_bfloat162(h2, h3);
    }

    float4* xq = (float4*)(out + (size_t)b * RE) + sub;
    float4 q = *xq;
    q.x += xres.x; q.y += xres.y; q.z += xres.z; q.w += xres.w;
    *xq = q;

    for (int o = 16; o > 0; o >>= 1) {
        sq += __shfl_down_sync(0xffffffffu, sq, o);
        rrn += __shfl_down_sync(0xffffffffu, rrn, o);
    }
    __shared__ float s_red[4][2][2];
    if (lane == 0) { s_red[grp][whalf][0] = sq; s_red[grp][whalf][1] = rrn; }
    __syncthreads();
    if (sub == 0) {
        g_lossrow[b] += s_red[grp][0][0] + s_red[grp][1][0];
        g_rr[b] = s_red[grp][0][1] + s_red[grp][1][1];
        out[OFF_IDX + (size_t)b * RNL + l] = (float)idx;
        out[OFF_OH + ((size_t)b * RNL + l) * RNE + idx] = 1.0f;
        g_keys[b] = 0xFFFFFFFFFFFFFFFFULL;   // reset for next layer
    }
}

// ---------------- deterministic final loss ----------------
__global__ void k_finish(float* __restrict__ out) {
    __shared__ float sm[256];
    int t = threadIdx.x;
    float s = 0.f;
    for (int i = t; i < RB; i += 256) s += g_lossrow[i];
    sm[t] = s;
    __syncthreads();
    for (int o = 128; o > 0; o >>= 1) {
        if (t < o) sm[t] += sm[t + o];
        __syncthreads();
    }
    if (t == 0) out[OFF_LOSS] = sm[0] * (1.25f / (3.0f * RB * RE));
}

// ---------------- launch: 2 streams, 3 events, 14 kernels (R14-proven graph) ----------------
extern "C" void kernel_launch(void* const* d_in, const int* in_sizes, int n_in,
                              void* d_out, int out_size) {
    const float* x = (const float*)d_in[0];
    const float* cbs = (const float*)d_in[1];
    float* out = (float*)d_out;

    cudaFuncSetAttribute(k_dist_tc, cudaFuncAttributeMaxDynamicSharedMemorySize, DYN_SM);

    cudaStream_t sH1;
    cudaStreamCreateWithFlags(&sH1, cudaStreamNonBlocking);
    cudaEvent_t eRoot, eInit, eH1;
    cudaEventCreateWithFlags(&eRoot, cudaEventDisableTiming);
    cudaEventCreateWithFlags(&eInit, cudaEventDisableTiming);
    cudaEventCreateWithFlags(&eH1, cudaEventDisableTiming);

    cudaEventRecord(eRoot, 0);
    cudaStreamWaitEvent(sH1, eRoot, 0);

    // single merged init (rows + all-layer codebook prep)
    k_init_all<<<RB + RNL * RNE, 64>>>(x, cbs, out);
    cudaEventRecord(eInit, 0);
    cudaStreamWaitEvent(sH1, eInit, 0);

    for (int l = 0; l < RNL; l++) {
        k_dist_tc<<<dim3(32, 32), 128, DYN_SM, 0>>>(l, 0, out);
        k_update<<<RB / 8, 256, 0, 0>>>(cbs, l, 0, out);
        k_dist_tc<<<dim3(32, 32), 128, DYN_SM, sH1>>>(l, RB / 2, out);
        k_update<<<RB / 8, 256, 0, sH1>>>(cbs, l, RB / 2, out);
    }

    cudaEventRecord(eH1, sH1);
    cudaStreamWaitEvent(0, eH1, 0);
    k_finish<<<1, 256>>>(out);
}

// round 17
// speedup vs baseline: 1.0403x; 1.0261x over previous
#include <cuda_runtime.h>
#include <cuda_bf16.h>
#include <cstdint>
#include <cstddef>

// ---------------- problem constants ----------------
#define RB 8192
#define RE 256
#define RNE 4096
#define RNL 3
#define K3 768           // split-bf16 K: [hi | lo | hi] x [hi | hi | lo]

// output layout (float32 elements), tuple order:
// x_q [B,E], mean_loss [1], all_idx [B,L], all_oh [B,L,n_e], all_logits [B,L,n_e]
static constexpr size_t LEN_XQ  = (size_t)RB * RE;                 // 2097152
static constexpr size_t OFF_LOSS = LEN_XQ;                         // 2097152
static constexpr size_t OFF_IDX  = OFF_LOSS + 1;                   // 2097153
static constexpr size_t LEN_IDX  = (size_t)RB * RNL;               // 24576
static constexpr size_t OFF_OH   = OFF_IDX + LEN_IDX;              // 2121729
static constexpr size_t LEN_OH   = (size_t)RB * RNL * RNE;         // 100663296
static constexpr size_t OFF_LG   = OFF_OH + LEN_OH;                // 102785025

// ---------------- device scratch ----------------
__device__ float g_res[RB * RE];                  // residual [B,E] fp32
__device__ float g_rr[RB];                        // ||residual_b||^2
__device__ float g_cc[RNL * RNE];                 // ||codebook row||^2 (fp32 exact)
__device__ unsigned long long g_keys[RB];         // packed (dist_bits<<32 | idx)
__device__ float g_lossrow[RB];                   // per-row accumulated sq error
__device__ __nv_bfloat16 g_Ap[(size_t)RB * K3];   // residual split  [hi|lo|hi]
__device__ __nv_bfloat16 g_Bp[(size_t)RNL * RNE * K3]; // codebook split [hi|hi|lo]

// ---------------- PTX helpers (sm_80-era only; no tcgen05 on plain sm_103) ----------------
__device__ __forceinline__ uint32_t smem_u32(const void* p) {
    uint32_t a;
    asm("{ .reg .u64 t; cvta.to.shared.u64 t, %1; cvt.u32.u64 %0, t; }" : "=r"(a) : "l"(p));
    return a;
}
__device__ __forceinline__ void cp16(uint32_t dst, const __nv_bfloat16* src) {
    asm volatile("cp.async.cg.shared.global [%0], [%1], 16;\n" :: "r"(dst),
                 "l"(__cvta_generic_to_global(src)));
}
__device__ __forceinline__ void cp_commit() {
    asm volatile("cp.async.commit_group;\n" ::: "memory");
}
template <int N>
__device__ __forceinline__ void cp_wait() {
    asm volatile("cp.async.wait_group %0;\n" :: "n"(N) : "memory");
}
__device__ __forceinline__ void ldsm4(uint32_t* r, uint32_t addr) {
    asm volatile("ldmatrix.sync.aligned.m8n8.x4.shared.b16 {%0,%1,%2,%3}, [%4];"
                 : "=r"(r[0]), "=r"(r[1]), "=r"(r[2]), "=r"(r[3]) : "r"(addr));
}
__device__ __forceinline__ void mma16816(float* c, const uint32_t* a, const uint32_t* b) {
    asm volatile(
        "mma.sync.aligned.m16n8k16.row.col.f32.bf16.bf16.f32 "
        "{%0,%1,%2,%3}, {%4,%5,%6,%7}, {%8,%9}, {%0,%1,%2,%3};"
        : "+f"(c[0]), "+f"(c[1]), "+f"(c[2]), "+f"(c[3])
        : "r"(a[0]), "r"(a[1]), "r"(a[2]), "r"(a[3]), "r"(b[0]), "r"(b[1]));
}
__device__ __forceinline__ void stcs(float* p, float v) {
    asm volatile("st.global.cs.f32 [%0], %1;" :: "l"(__cvta_generic_to_global(p)), "f"(v));
}
__device__ __forceinline__ void stcs2(float* p, float2 v) {
    asm volatile("st.global.cs.v2.f32 [%0], {%1, %2};"
                 :: "l"(__cvta_generic_to_global(p)), "f"(v.x), "f"(v.y));
}

// split fp32 -> (hi, lo) bf16
__device__ __forceinline__ void split1(float x, __nv_bfloat16& h, __nv_bfloat16& l) {
    h = __float2bfloat16(x);
    l = __float2bfloat16(__fsub_rn(x, __bfloat162float(h)));
}

// ---------------- merged init: rows (residual/xq/rr/keys/loss/A') + codebook (B'/cc) ----------------
__global__ void k_init_all(const float* __restrict__ x, const float* __restrict__ cbs,
                           float* __restrict__ out) {
    int blk = blockIdx.x, t = threadIdx.x;  // 64 threads
    if (blk < RB) {
        int b = blk;
        float4 v = *(const float4*)(x + (size_t)b * RE + t * 4);
        *(float4*)(g_res + (size_t)b * RE + t * 4) = v;
        *(float4*)(out + (size_t)b * RE + t * 4) = make_float4(0.f, 0.f, 0.f, 0.f);

        __nv_bfloat16 h0, h1, h2, h3, l0, l1, l2, l3;
        split1(v.x, h0, l0); split1(v.y, h1, l1); split1(v.z, h2, l2); split1(v.w, h3, l3);
        __nv_bfloat16* ap = g_Ap + (size_t)b * K3 + t * 4;
        *(__nv_bfloat162*)(ap + 0) = __nv_bfloat162(h0, h1);
        *(__nv_bfloat162*)(ap + 2) = __nv_bfloat162(h2, h3);
        *(__nv_bfloat162*)(ap + 256) = __nv_bfloat162(l0, l1);
        *(__nv_bfloat162*)(ap + 258) = __nv_bfloat162(l2, l3);
        *(__nv_bfloat162*)(ap + 512) = __nv_bfloat162(h0, h1);
        *(__nv_bfloat162*)(ap + 514) = __nv_bfloat162(h2, h3);

        float s = v.x * v.x + v.y * v.y + v.z * v.z + v.w * v.w;
        for (int o = 16; o > 0; o >>= 1) s += __shfl_down_sync(0xffffffffu, s, o);
        __shared__ float sm[2];
        if ((t & 31) == 0) sm[t >> 5] = s;
        __syncthreads();
        if (t == 0) {
            g_rr[b] = sm[0] + sm[1];
            g_keys[b] = 0xFFFFFFFFFFFFFFFFULL;
            g_lossrow[b] = 0.f;
        }
    } else {
        int i = blk - RB;  // [0, RNL*RNE)
        float4 v = *(const float4*)(cbs + (size_t)i * RE + t * 4);
        __nv_bfloat16 h0, h1, h2, h3, l0, l1, l2, l3;
        split1(v.x, h0, l0); split1(v.y, h1, l1); split1(v.z, h2, l2); split1(v.w, h3, l3);
        __nv_bfloat16* bp = g_Bp + (size_t)i * K3 + t * 4;
        *(__nv_bfloat162*)(bp + 0) = __nv_bfloat162(h0, h1);
        *(__nv_bfloat162*)(bp + 2) = __nv_bfloat162(h2, h3);
        *(__nv_bfloat162*)(bp + 256) = __nv_bfloat162(h0, h1);
        *(__nv_bfloat162*)(bp + 258) = __nv_bfloat162(h2, h3);
        *(__nv_bfloat162*)(bp + 512) = __nv_bfloat162(l0, l1);
        *(__nv_bfloat162*)(bp + 514) = __nv_bfloat162(l2, l3);

        float s = v.x * v.x + v.y * v.y + v.z * v.z + v.w * v.w;
        for (int o = 16; o > 0; o >>= 1) s += __shfl_down_sync(0xffffffffu, s, o);
        __shared__ float sm[2];
        if ((t & 31) == 0) sm[t >> 5] = s;
        __syncthreads();
        if (t == 0) g_cc[i] = sm[0] + sm[1];
    }
}

// ---------------- mma.sync distance GEMM + logits + OH-zero + argmin ----------------
// CTA 128x128, 4 warps (2m x 2n), warp tile 64x64, K=768 in 12 chunks of 64.
// 3-stage cp.async pipeline (32KB/stage), ONE __syncthreads per chunk.
// One-hot tile zeroing is spread across the mainloop chunks (result-independent
// streaming stores hidden under MMA); epilogue stores only the logits.
// Grid = (32, 32) per row-half; m_base selects the half.
#define DYN_SM 99328

__global__ void __launch_bounds__(128, 2) k_dist_tc(int l, int m_base, float* __restrict__ out) {
    extern __shared__ __align__(16) char smraw[];
    uint32_t rawb = smem_u32(smraw);
    uint32_t sbase = (rawb + 1023u) & ~1023u;
    float* ep = (float*)(smraw + (sbase - rawb));  // epilogue staging [128][132]

    int tid = threadIdx.x, wid = tid >> 5, lane = tid & 31;
    int n0 = blockIdx.x * 128, m0 = m_base + blockIdx.y * 128;
    int warp_m = wid >> 1, warp_n = wid & 1;
    int mbw = warp_m * 64, nbw = warp_n * 64;
    int g = lane >> 2, tig = lane & 3;

    const __nv_bfloat16* Ap = g_Ap;
    const __nv_bfloat16* Bp = g_Bp + (size_t)l * RNE * K3;
    const float* ccn = g_cc + l * RNE;

    // per-lane ldmatrix address pieces (4 A frags of m16, 4 B frags of n16)
    uint32_t arow[4], axor[4], brow[4], bxor[4];
#pragma unroll
    for (int i = 0; i < 4; i++) {
        int r = mbw + i * 16 + ((lane >> 3) & 1) * 8 + (lane & 7);
        arow[i] = (uint32_t)r * 128u;
        axor[i] = (uint32_t)((r & 7) << 4);
    }
    uint32_t koffA = (uint32_t)(((lane >> 4) & 1) * 16);
#pragma unroll
    for (int j2 = 0; j2 < 4; j2++) {
        int r = nbw + j2 * 16 + ((lane >> 4) & 1) * 8 + (lane & 7);
        brow[j2] = (uint32_t)r * 128u;
        bxor[j2] = (uint32_t)((r & 7) << 4);
    }
    uint32_t koffB = (uint32_t)(((lane >> 3) & 1) * 16);

    float acc[4][8][4];
#pragma unroll
    for (int i = 0; i < 4; i++)
#pragma unroll
        for (int j = 0; j < 8; j++)
#pragma unroll
            for (int r = 0; r < 4; r++) acc[i][j][r] = 0.f;

    // chunk loader: 128 rows x 64 bf16 (128B rows), SW128 swizzle, A then B
    auto load_chunk = [&](int c, int s) {
        uint32_t ab = sbase + s * 32768;
        uint32_t bb = ab + 16384;
        const __nv_bfloat16* ag = Ap + (size_t)m0 * K3 + c * 64;
        const __nv_bfloat16* bg = Bp + (size_t)n0 * K3 + c * 64;
#pragma unroll
        for (int i = 0; i < 8; i++) {
            int idx = tid + i * 128;
            int row = idx >> 3, q = idx & 7;
            uint32_t off = row * 128 + q * 16;
            uint32_t sw = off ^ ((off >> 3) & 0x70);
            cp16(ab + sw, ag + (size_t)row * K3 + q * 8);
        }
#pragma unroll
        for (int i = 0; i < 8; i++) {
            int idx = tid + i * 128;
            int row = idx >> 3, q = idx & 7;
            uint32_t off = row * 128 + q * 16;
            uint32_t sw = off ^ ((off >> 3) & 0x70);
            cp16(bb + sw, bg + (size_t)row * K3 + q * 8);
        }
        cp_commit();
    };

    load_chunk(0, 0);
    load_chunk(1, 1);
    int stage_next = 2;
    for (int c = 0; c < 12; c++) {
        int s = c % 3;
        if (c == 11) cp_wait<0>(); else cp_wait<1>();
        __syncthreads();  // chunk c visible; orders prior readers vs upcoming overwrite

        uint32_t sA = sbase + s * 32768;
        uint32_t sB = sA + 16384;
#pragma unroll
        for (int ks = 0; ks < 4; ks++) {
            uint32_t a[4][4], b[4][4];
#pragma unroll
            for (int i = 0; i < 4; i++)
                ldsm4(a[i], sA + arow[i] + (((uint32_t)(ks * 32) + koffA) ^ axor[i]));
#pragma unroll
            for (int j2 = 0; j2 < 4; j2++)
                ldsm4(b[j2], sB + brow[j2] + (((uint32_t)(ks * 32) + koffB) ^ bxor[j2]));
#pragma unroll
            for (int i = 0; i < 4; i++)
#pragma unroll
                for (int j = 0; j < 8; j++)
                    mma16816(acc[i][j], a[i], &b[j >> 1][(j & 1) * 2]);
        }
        if (c + 2 < 12) {
            load_chunk(c + 2, stage_next);
            stage_next = (stage_next + 1) % 3;
        }
        // one-hot tile zeroing spread across chunks (hidden under MMA):
        // rows [11c, 11c+11) of the 128-row tile, coalesced, streaming hint
#pragma unroll
        for (int k = 0; k < 11; k++) {
            int r = c * 11 + k;
            if (r < 128)
                stcs(out + OFF_OH + ((size_t)(m0 + r) * RNL + l) * RNE + n0 + tid, 0.0f);
        }
    }
    __syncthreads();  // all warps done reading stages before epilogue reuses smem

    // ---- epilogue: d = (rr + cc) - 2*dot, argmin keys, stage logits ----
    float cc0[8], cc1[8];
#pragma unroll
    for (int j = 0; j < 8; j++) {
        cc0[j] = ccn[n0 + nbw + j * 8 + tig * 2];
        cc1[j] = ccn[n0 + nbw + j * 8 + tig * 2 + 1];
    }
#pragma unroll
    for (int i = 0; i < 4; i++) {
        int r0 = mbw + i * 16 + g, r1 = r0 + 8;
        float rr0 = g_rr[m0 + r0], rr1 = g_rr[m0 + r1];
        unsigned long long b0 = 0xFFFFFFFFFFFFFFFFULL, b1 = b0;
#pragma unroll
        for (int j = 0; j < 8; j++) {
            int coln = nbw + j * 8 + tig * 2;
            unsigned nlo = (unsigned)(n0 + coln), nhi = nlo + 1;
            float d00 = __fadd_rn(__fadd_rn(rr0, cc0[j]), -2.0f * acc[i][j][0]);
            float d01 = __fadd_rn(__fadd_rn(rr0, cc1[j]), -2.0f * acc[i][j][1]);
            float d10 = __fadd_rn(__fadd_rn(rr1, cc0[j]), -2.0f * acc[i][j][2]);
            float d11 = __fadd_rn(__fadd_rn(rr1, cc1[j]), -2.0f * acc[i][j][3]);
            *(float2*)(ep + r0 * 132 + coln) = make_float2(d00, d01);
            *(float2*)(ep + r1 * 132 + coln) = make_float2(d10, d11);
            unsigned long long k00 = ((unsigned long long)__float_as_uint(d00) << 32) | nlo;
            unsigned long long k01 = ((unsigned long long)__float_as_uint(d01) << 32) | nhi;
            unsigned long long k10 = ((unsigned long long)__float_as_uint(d10) << 32) | nlo;
            unsigned long long k11 = ((unsigned long long)__float_as_uint(d11) << 32) | nhi;
            if (k00 < b0) b0 = k00;
            if (k01 < b0) b0 = k01;
            if (k10 < b1) b1 = k10;
            if (k11 < b1) b1 = k11;
        }
        b0 = min(b0, __shfl_xor_sync(0xffffffffu, b0, 1));
        b0 = min(b0, __shfl_xor_sync(0xffffffffu, b0, 2));
        b1 = min(b1, __shfl_xor_sync(0xffffffffu, b1, 1));
        b1 = min(b1, __shfl_xor_sync(0xffffffffu, b1, 2));
        if (tig == 0) {
            atomicMin(&g_keys[m0 + r0], b0);
            atomicMin(&g_keys[m0 + r1], b1);
        }
    }
    __syncthreads();

    // coalesced logits store: 128 threads, one row per iteration (streaming hint)
    for (int r = 0; r < 128; r++) {
        stcs(out + OFF_LG + ((size_t)(m0 + r) * RNL + l) * RNE + n0 + tid, ep[r * 132 + tid]);
    }
}

// ---------------- per-row gather/update: 256 threads, 4 rows per block ----------------
// Writes the one-hot 1.0 directly (its OH tile was zeroed by dist in the same stream).
__global__ void k_update(const float* __restrict__ cbs, int l, int row_base,
                         float* __restrict__ out) {
    int tid = threadIdx.x;
    int grp = tid >> 6;          // 0..3 (four 64-thread groups = 4 rows)
    int sub = tid & 63;          // position within row
    int lane = tid & 31;
    int whalf = (tid >> 5) & 1;  // warp half within group
    int b = row_base + blockIdx.x * 4 + grp;

    unsigned long long key = g_keys[b];
    unsigned idx = (unsigned)(key & 0xFFFFFFFFULL);
    const float* cbL = cbs + (size_t)l * RNE * RE;
    float4 c4 = *(const float4*)(cbL + (size_t)idx * RE + sub * 4);
    float4 r4 = *(float4*)(g_res + (size_t)b * RE + sub * 4);

    float sq = 0.f, rrn = 0.f;
    float4 xres, nr;
#define STEP(comp)                                           \
    {                                                        \
        float df = __fsub_rn(c4.comp, r4.comp);              \
        float xr = __fadd_rn(r4.comp, df);                   \
        float nv = __fsub_rn(r4.comp, xr);                   \
        sq = fmaf(df, df, sq); rrn = fmaf(nv, nv, rrn);      \
        xres.comp = xr; nr.comp = nv;                        \
    }
    STEP(x) STEP(y) STEP(z) STEP(w)
#undef STEP

    *(float4*)(g_res + (size_t)b * RE + sub * 4) = nr;

    if (l < RNL - 1) {  // refresh A' for next layer
        __nv_bfloat16 h0, h1, h2, h3, l0, l1, l2, l3;
        split1(nr.x, h0, l0); split1(nr.y, h1, l1); split1(nr.z, h2, l2); split1(nr.w, h3, l3);
        __nv_bfloat16* ap = g_Ap + (size_t)b * K3 + sub * 4;
        *(__nv_bfloat162*)(ap + 0) = __nv_bfloat162(h0, h1);
        *(__nv_bfloat162*)(ap + 2) = __nv_bfloat162(h2, h3);
        *(__nv_bfloat162*)(ap + 256) = __nv_bfloat162(l0, l1);
        *(__nv_bfloat162*)(ap + 258) = __nv_bfloat162(l2, l3);
        *(__nv_bfloat162*)(ap + 512) = __nv_bfloat162(h0, h1);
        *(__nv_bfloat162*)(ap + 514) = __nv_bfloat162(h2, h3);
    }

    float4* xq = (float4*)(out + (size_t)b * RE) + sub;
    float4 q = *xq;
    q.x += xres.x; q.y += xres.y; q.z += xres.z; q.w += xres.w;
    *xq = q;

    for (int o = 16; o > 0; o >>= 1) {
        sq += __shfl_down_sync(0xffffffffu, sq, o);
        rrn += __shfl_down_sync(0xffffffffu, rrn, o);
    }
    __shared__ float s_red[4][2][2];
    if (lane == 0) { s_red[grp][whalf][0] = sq; s_red[grp][whalf][1] = rrn; }
    __syncthreads();
    if (sub == 0) {
        g_lossrow[b] += s_red[grp][0][0] + s_red[grp][1][0];
        g_rr[b] = s_red[grp][0][1] + s_red[grp][1][1];
        out[OFF_IDX + (size_t)b * RNL + l] = (float)idx;
        out[OFF_OH + ((size_t)b * RNL + l) * RNE + idx] = 1.0f;
        g_keys[b] = 0xFFFFFFFFFFFFFFFFULL;   // reset for next layer
    }
}

// ---------------- deterministic final loss ----------------
__global__ void k_finish(float* __restrict__ out) {
    __shared__ float sm[256];
    int t = threadIdx.x;
    float s = 0.f;
    for (int i = t; i < RB; i += 256) s += g_lossrow[i];
    sm[t] = s;
    __syncthreads();
    for (int o = 128; o > 0; o >>= 1) {
        if (t < o) sm[t] += sm[t + o];
        __syncthreads();
    }
    if (t == 0) out[OFF_LOSS] = sm[0] * (1.25f / (3.0f * RB * RE));
}

// ---------------- launch: 2 streams, 3 events, 14 kernels (R14-proven graph) ----------------
extern "C" void kernel_launch(void* const* d_in, const int* in_sizes, int n_in,
                              void* d_out, int out_size) {
    const float* x = (const float*)d_in[0];
    const float* cbs = (const float*)d_in[1];
    float* out = (float*)d_out;

    cudaFuncSetAttribute(k_dist_tc, cudaFuncAttributeMaxDynamicSharedMemorySize, DYN_SM);

    cudaStream_t sH1;
    cudaStreamCreateWithFlags(&sH1, cudaStreamNonBlocking);
    cudaEvent_t eRoot, eInit, eH1;
    cudaEventCreateWithFlags(&eRoot, cudaEventDisableTiming);
    cudaEventCreateWithFlags(&eInit, cudaEventDisableTiming);
    cudaEventCreateWithFlags(&eH1, cudaEventDisableTiming);

    cudaEventRecord(eRoot, 0);
    cudaStreamWaitEvent(sH1, eRoot, 0);

    // single merged init (rows + all-layer codebook prep)
    k_init_all<<<RB + RNL * RNE, 64>>>(x, cbs, out);
    cudaEventRecord(eInit, 0);
    cudaStreamWaitEvent(sH1, eInit, 0);

    for (int l = 0; l < RNL; l++) {
        k_dist_tc<<<dim3(32, 32), 128, DYN_SM, 0>>>(l, 0, out);
        k_update<<<RB / 8, 256, 0, 0>>>(cbs, l, 0, out);
        k_dist_tc<<<dim3(32, 32), 128, DYN_SM, sH1>>>(l, RB / 2, out);
        k_update<<<RB / 8, 256, 0, sH1>>>(cbs, l, RB / 2, out);
    }

    cudaEventRecord(eH1, sH1);
    cudaStreamWaitEvent(0, eH1, 0);
    k_finish<<<1, 256>>>(out);
}